// round 1
// baseline (speedup 1.0000x reference)
#include <cuda_runtime.h>
#include <cstdint>

// ---------------------------------------------------------------------------
// FCOS head: 5 levels, batch 2, C=256, 2 towers (4x conv3x3+GN(32)+ReLU),
// heads: cls(80), bbox(4,relu), ctr(1), dim(3), ori(1), kp(16), depth(1).
// Output layout: [cls | bbox | ctr | dim | ori | kp | depth], each
// [N, TotalPos, c] with levels concatenated along pos.
// ---------------------------------------------------------------------------

#define TP 20267          // total positions per batch item
#define ICH 256
#define KCH 8
#define BN 64

// scratch (2*256*100*152 floats = max level tensor)
__device__ float g_bufA[7782400];
__device__ float g_bufB[7782400];
__device__ float g_mean[64];
__device__ float g_inv[64];
__device__ float g_regw[26 * 256 * 9];
__device__ float g_regb[26];

// per-packed-reg-oc output metadata: section base (elements), channels in
// section, channel index, relu flag.
__constant__ long long c_base[26] = {
    3242720LL, 3242720LL, 3242720LL, 3242720LL,                    // bbox
    3404856LL,                                                     // ctr
    3445390LL, 3445390LL, 3445390LL,                               // dim
    3566992LL,                                                     // ori
    3607526LL, 3607526LL, 3607526LL, 3607526LL, 3607526LL, 3607526LL,
    3607526LL, 3607526LL, 3607526LL, 3607526LL, 3607526LL, 3607526LL,
    3607526LL, 3607526LL, 3607526LL, 3607526LL,                    // kp
    4256070LL};                                                    // depth
__constant__ int c_ctot[26] = {4, 4, 4, 4, 1, 3, 3, 3, 1,
                               16, 16, 16, 16, 16, 16, 16, 16,
                               16, 16, 16, 16, 16, 16, 16, 16, 1};
__constant__ int c_ch[26] = {0, 1, 2, 3, 0, 0, 1, 2, 0,
                             0, 1, 2, 3, 4, 5, 6, 7,
                             8, 9, 10, 11, 12, 13, 14, 15, 0};
__constant__ int c_relu[26] = {1, 1, 1, 1, 0, 0, 0, 0, 0,
                               0, 0, 0, 0, 0, 0, 0, 0,
                               0, 0, 0, 0, 0, 0, 0, 0, 0};

// ---------------------------------------------------------------------------
// Pack reg-head weights/biases into one [26,256,9] conv
// ---------------------------------------------------------------------------
__global__ void pack_reg(const float* __restrict__ bbox_w, const float* __restrict__ bbox_b,
                         const float* __restrict__ ctr_w,  const float* __restrict__ ctr_b,
                         const float* __restrict__ dim_w,  const float* __restrict__ dim_b,
                         const float* __restrict__ ori_w,  const float* __restrict__ ori_b,
                         const float* __restrict__ kp_w,   const float* __restrict__ kp_b,
                         const float* __restrict__ depth_w,const float* __restrict__ depth_b) {
    int idx = blockIdx.x * blockDim.x + threadIdx.x;
    int total = 26 * 2304;
    if (idx < total) {
        int oc = idx / 2304;
        int r = idx % 2304;
        const float* src;
        if (oc < 4)       src = bbox_w + oc * 2304;
        else if (oc == 4) src = ctr_w;
        else if (oc < 8)  src = dim_w + (oc - 5) * 2304;
        else if (oc == 8) src = ori_w;
        else if (oc < 25) src = kp_w + (oc - 9) * 2304;
        else              src = depth_w;
        g_regw[idx] = src[r];
    }
    if (idx < 26) {
        float b;
        if (idx < 4)       b = bbox_b[idx];
        else if (idx == 4) b = ctr_b[0];
        else if (idx < 8)  b = dim_b[idx - 5];
        else if (idx == 8) b = ori_b[0];
        else if (idx < 25) b = kp_b[idx - 9];
        else               b = depth_b[0];
        g_regb[idx] = b;
    }
}

// ---------------------------------------------------------------------------
// Tower conv: 3x3 SAME, IC=OC=256, tile 64 oc x 64 cols of one output row.
// grid: (ceil(W/64), H, N*4), block 256.
// ---------------------------------------------------------------------------
__global__ __launch_bounds__(256) void conv_tower(
    const float* __restrict__ x, const float* __restrict__ w,
    const float* __restrict__ bias, float* __restrict__ y, int H, int W) {
    __shared__ __align__(16) float sw[64][KCH][12];
    __shared__ __align__(16) float sx[KCH][3][BN + 4];

    int n = blockIdx.z >> 2;
    int oc0 = (blockIdx.z & 3) * 64;
    int y0 = blockIdx.y;
    int x0 = blockIdx.x * BN;
    int tid = threadIdx.x;
    int ocq = tid >> 4;
    int colq = tid & 15;

    float acc[4][4] = {};

    for (int ic0 = 0; ic0 < ICH; ic0 += KCH) {
        for (int idx = tid; idx < 64 * KCH * 9; idx += 256) {
            int oc = idx / (KCH * 9);
            int r = idx % (KCH * 9);
            int kc = r / 9, t = r % 9;
            sw[oc][kc][t] = w[((oc0 + oc) * ICH + ic0 + kc) * 9 + t];
        }
        for (int idx = tid; idx < KCH * 3 * (BN + 2); idx += 256) {
            int kc = idx / (3 * (BN + 2));
            int r = idx % (3 * (BN + 2));
            int ry = r / (BN + 2), cx = r % (BN + 2);
            int gy = y0 - 1 + ry, gx = x0 - 1 + cx;
            float v = 0.f;
            if (gy >= 0 && gy < H && gx >= 0 && gx < W)
                v = x[((size_t)(n * ICH + ic0 + kc) * H + gy) * W + gx];
            sx[kc][ry][cx] = v;
        }
        __syncthreads();

#pragma unroll
        for (int kc = 0; kc < KCH; kc++) {
            float wr[4][9];
#pragma unroll
            for (int i = 0; i < 4; i++) {
                float4 a = *(const float4*)&sw[ocq * 4 + i][kc][0];
                float4 b = *(const float4*)&sw[ocq * 4 + i][kc][4];
                wr[i][0] = a.x; wr[i][1] = a.y; wr[i][2] = a.z; wr[i][3] = a.w;
                wr[i][4] = b.x; wr[i][5] = b.y; wr[i][6] = b.z; wr[i][7] = b.w;
                wr[i][8] = sw[ocq * 4 + i][kc][8];
            }
#pragma unroll
            for (int ky = 0; ky < 3; ky++) {
                float xr[6];
                float4 a = *(const float4*)&sx[kc][ky][colq * 4];
                xr[0] = a.x; xr[1] = a.y; xr[2] = a.z; xr[3] = a.w;
                xr[4] = sx[kc][ky][colq * 4 + 4];
                xr[5] = sx[kc][ky][colq * 4 + 5];
#pragma unroll
                for (int kx = 0; kx < 3; kx++)
#pragma unroll
                    for (int i = 0; i < 4; i++)
#pragma unroll
                        for (int j = 0; j < 4; j++)
                            acc[i][j] += wr[i][ky * 3 + kx] * xr[j + kx];
            }
        }
        __syncthreads();
    }

#pragma unroll
    for (int i = 0; i < 4; i++) {
        int oc = oc0 + ocq * 4 + i;
        float b = bias[oc];
#pragma unroll
        for (int j = 0; j < 4; j++) {
            int gx = x0 + colq * 4 + j;
            if (gx < W)
                y[((size_t)(n * ICH + oc) * H + y0) * W + gx] = acc[i][j] + b;
        }
    }
}

// ---------------------------------------------------------------------------
// GroupNorm stats: one block per (n, group). groups=32, 8 ch/group.
// ---------------------------------------------------------------------------
__global__ void gn_reduce(const float* __restrict__ x, int HW) {
    int ng = blockIdx.x;
    int n = ng >> 5, g = ng & 31;
    const float* base = x + (size_t)(n * 256 + g * 8) * HW;
    int M = 8 * HW;
    float s = 0.f, sq = 0.f;
    for (int i = threadIdx.x; i < M; i += blockDim.x) {
        float v = base[i];
        s += v;
        sq += v * v;
    }
    __shared__ float ss[256], ssq[256];
    int tid = threadIdx.x;
    ss[tid] = s; ssq[tid] = sq;
    __syncthreads();
    for (int off = 128; off > 0; off >>= 1) {
        if (tid < off) { ss[tid] += ss[tid + off]; ssq[tid] += ssq[tid + off]; }
        __syncthreads();
    }
    if (tid == 0) {
        float mu = ss[0] / M;
        float var = ssq[0] / M - mu * mu;
        g_mean[ng] = mu;
        g_inv[ng] = rsqrtf(var + 1e-5f);
    }
}

__global__ void gn_apply(float* __restrict__ x, const float* __restrict__ gamma,
                         const float* __restrict__ beta, int HW, int total) {
    int i = blockIdx.x * blockDim.x + threadIdx.x;
    if (i >= total) return;
    int c = (i / HW) & 255;
    int n = i / (HW * 256);
    int ng = n * 32 + (c >> 3);
    float v = (x[i] - g_mean[ng]) * g_inv[ng] * gamma[c] + beta[c];
    x[i] = fmaxf(v, 0.f);
}

// ---------------------------------------------------------------------------
// Head conv: 3x3 SAME, IC=256, OC<=96, tile 32 oc x 64 cols. Writes directly
// into d_out. mode 0 = cls (OC=80), mode 1 = packed reg (OC=26).
// grid: (ceil(W/64), H, N*ceil(OC/32)), block 256.
// ---------------------------------------------------------------------------
__global__ __launch_bounds__(256) void conv_head(
    const float* __restrict__ x, const float* __restrict__ w,
    const float* __restrict__ bias, float* __restrict__ out,
    int H, int W, int OC, int levelBase, int mode) {
    __shared__ __align__(16) float sw[32][KCH][12];
    __shared__ __align__(16) float sx[KCH][3][BN + 4];

    int ocBlocks = (OC + 31) >> 5;
    int n = blockIdx.z / ocBlocks;
    int oc0 = (blockIdx.z % ocBlocks) * 32;
    int y0 = blockIdx.y;
    int x0 = blockIdx.x * BN;
    int tid = threadIdx.x;
    int ocq = tid >> 4;
    int colq = tid & 15;

    float acc[2][4] = {};

    for (int ic0 = 0; ic0 < ICH; ic0 += KCH) {
        for (int idx = tid; idx < 32 * KCH * 9; idx += 256) {
            int oc = idx / (KCH * 9);
            int r = idx % (KCH * 9);
            int kc = r / 9, t = r % 9;
            sw[oc][kc][t] = (oc0 + oc < OC)
                                ? w[((oc0 + oc) * ICH + ic0 + kc) * 9 + t]
                                : 0.f;
        }
        for (int idx = tid; idx < KCH * 3 * (BN + 2); idx += 256) {
            int kc = idx / (3 * (BN + 2));
            int r = idx % (3 * (BN + 2));
            int ry = r / (BN + 2), cx = r % (BN + 2);
            int gy = y0 - 1 + ry, gx = x0 - 1 + cx;
            float v = 0.f;
            if (gy >= 0 && gy < H && gx >= 0 && gx < W)
                v = x[((size_t)(n * ICH + ic0 + kc) * H + gy) * W + gx];
            sx[kc][ry][cx] = v;
        }
        __syncthreads();

#pragma unroll
        for (int kc = 0; kc < KCH; kc++) {
            float wr[2][9];
#pragma unroll
            for (int i = 0; i < 2; i++) {
                float4 a = *(const float4*)&sw[ocq * 2 + i][kc][0];
                float4 b = *(const float4*)&sw[ocq * 2 + i][kc][4];
                wr[i][0] = a.x; wr[i][1] = a.y; wr[i][2] = a.z; wr[i][3] = a.w;
                wr[i][4] = b.x; wr[i][5] = b.y; wr[i][6] = b.z; wr[i][7] = b.w;
                wr[i][8] = sw[ocq * 2 + i][kc][8];
            }
#pragma unroll
            for (int ky = 0; ky < 3; ky++) {
                float xr[6];
                float4 a = *(const float4*)&sx[kc][ky][colq * 4];
                xr[0] = a.x; xr[1] = a.y; xr[2] = a.z; xr[3] = a.w;
                xr[4] = sx[kc][ky][colq * 4 + 4];
                xr[5] = sx[kc][ky][colq * 4 + 5];
#pragma unroll
                for (int kx = 0; kx < 3; kx++)
#pragma unroll
                    for (int i = 0; i < 2; i++)
#pragma unroll
                        for (int j = 0; j < 4; j++)
                            acc[i][j] += wr[i][ky * 3 + kx] * xr[j + kx];
            }
        }
        __syncthreads();
    }

#pragma unroll
    for (int i = 0; i < 2; i++) {
        int oc = oc0 + ocq * 2 + i;
        if (oc >= OC) continue;
        float b = bias[oc];
#pragma unroll
        for (int j = 0; j < 4; j++) {
            int gx = x0 + colq * 4 + j;
            if (gx >= W) continue;
            float v = acc[i][j] + b;
            long long unit = (long long)n * TP + levelBase + (long long)y0 * W + gx;
            long long addr;
            if (mode == 0) {
                addr = unit * 80 + oc;          // cls section at base 0
            } else {
                addr = c_base[oc] + unit * c_ctot[oc] + c_ch[oc];
                if (c_relu[oc]) v = fmaxf(v, 0.f);
            }
            out[addr] = v;
        }
    }
}

// ---------------------------------------------------------------------------
// Host orchestration
// ---------------------------------------------------------------------------
extern "C" void kernel_launch(void* const* d_in, const int* in_sizes, int n_in,
                              void* d_out, int out_size) {
    const float* feats[5];
    for (int i = 0; i < 5; i++) feats[i] = (const float*)d_in[i];
    const float* cls_conv_w = (const float*)d_in[5];
    const float* cls_conv_b = (const float*)d_in[6];
    const float* cls_gn_w = (const float*)d_in[7];
    const float* cls_gn_b = (const float*)d_in[8];
    const float* cls_out_w = (const float*)d_in[9];
    const float* cls_out_b = (const float*)d_in[10];
    const float* reg_conv_w = (const float*)d_in[11];
    const float* reg_conv_b = (const float*)d_in[12];
    const float* reg_gn_w = (const float*)d_in[13];
    const float* reg_gn_b = (const float*)d_in[14];
    float* out = (float*)d_out;

    float *bufA, *bufB, *regw, *regb;
    cudaGetSymbolAddress((void**)&bufA, g_bufA);
    cudaGetSymbolAddress((void**)&bufB, g_bufB);
    cudaGetSymbolAddress((void**)&regw, g_regw);
    cudaGetSymbolAddress((void**)&regb, g_regb);

    pack_reg<<<(26 * 2304 + 255) / 256, 256>>>(
        (const float*)d_in[15], (const float*)d_in[16],   // bbox
        (const float*)d_in[17], (const float*)d_in[18],   // ctr
        (const float*)d_in[19], (const float*)d_in[20],   // dim
        (const float*)d_in[21], (const float*)d_in[22],   // ori
        (const float*)d_in[23], (const float*)d_in[24],   // kp
        (const float*)d_in[25], (const float*)d_in[26]);  // depth

    const int Hs[5] = {100, 50, 25, 13, 7};
    const int Ws[5] = {152, 76, 38, 19, 10};
    const int lvlBase[5] = {0, 15200, 19000, 19950, 20197};

    for (int lvl = 0; lvl < 5; lvl++) {
        int H = Hs[lvl], W = Ws[lvl];
        int HW = H * W;
        int total = 2 * 256 * HW;
        dim3 gConv((W + BN - 1) / BN, H, 2 * 4);
        int gApply = (total + 255) / 256;

        // --- cls tower ---
        const float* cur = feats[lvl];
        float* bufs[2] = {bufA, bufB};
        for (int s = 0; s < 4; s++) {
            float* dst = bufs[s & 1];
            conv_tower<<<gConv, 256>>>(cur, cls_conv_w + (size_t)s * 256 * 256 * 9,
                                       cls_conv_b + s * 256, dst, H, W);
            gn_reduce<<<64, 256>>>(dst, HW);
            gn_apply<<<gApply, 256>>>(dst, cls_gn_w + s * 256, cls_gn_b + s * 256,
                                      HW, total);
            cur = dst;
        }
        {
            dim3 gHead((W + BN - 1) / BN, H, 2 * 3);  // OC=80 -> 3 oc blocks
            conv_head<<<gHead, 256>>>(cur, cls_out_w, cls_out_b, out, H, W, 80,
                                      lvlBase[lvl], 0);
        }

        // --- reg tower ---
        cur = feats[lvl];
        for (int s = 0; s < 4; s++) {
            float* dst = bufs[s & 1];
            conv_tower<<<gConv, 256>>>(cur, reg_conv_w + (size_t)s * 256 * 256 * 9,
                                       reg_conv_b + s * 256, dst, H, W);
            gn_reduce<<<64, 256>>>(dst, HW);
            gn_apply<<<gApply, 256>>>(dst, reg_gn_w + s * 256, reg_gn_b + s * 256,
                                      HW, total);
            cur = dst;
        }
        {
            dim3 gHead((W + BN - 1) / BN, H, 2 * 1);  // OC=26 -> 1 oc block
            conv_head<<<gHead, 256>>>(cur, regw, regb, out, H, W, 26,
                                      lvlBase[lvl], 1);
        }
    }
    (void)in_sizes; (void)n_in; (void)out_size;
}